// round 11
// baseline (speedup 1.0000x reference)
#include <cuda_runtime.h>
#include <cuda_fp16.h>
#include <mma.h>
#include <cstdint>

using namespace nvcuda;

#define N_NODES 100000
#define NE      1600000
#define D       128
#define NB      ((N_NODES + 255) / 256)

#define GEMM_TILES    782                 // 128 rows each
#define GEMM_BLOCKS   296                 // persistent: 2 per SM x 148
#define EDGE_BLOCKS   1563                // 1024 edges per block (256 thr x 4)
#define SCAN_BLOCKS   49                  // 2048 nodes per block

// smem layout for fused_A GEMM blocks: W (64 KB) + C staging (32 KB)
#define SMEM_W_FLOATS (D * D)                      // 16384
#define SMEM_C_FLOATS (8 * 16 * 64)                // 8 warps x 16 rows x 64 cols
#define SMEM_TOTAL_B  ((SMEM_W_FLOATS + SMEM_C_FLOATS) * (int)sizeof(float))  // 96 KB

// Scratch (__device__ globals; no allocation)
__device__ __align__(16) __half g_Yh[(size_t)N_NODES * D];  // 25.6 MB
__device__ int g_degi[N_NODES];
__device__ int g_rowstart[N_NODES];
__device__ int g_cursor[N_NODES];
__device__ int g_adj[2 * NE];              // 12.8 MB
__device__ int g_bsum[SCAN_BLOCKS];
__device__ unsigned int g_sync;            // monotonic across calls; never reset
__device__ int g_is64;

// ---------------------------------------------------------------------------
// probe (thread 0) + zero degrees.
// ---------------------------------------------------------------------------
__global__ void probe_zero_kernel(const int* __restrict__ ei) {
    int i = blockIdx.x * blockDim.x + threadIdx.x;
    if (i == 0) {
        int acc = 0;
#pragma unroll
        for (int k = 1; k < 32; k += 2) acc |= ei[k];
        g_is64 = (acc == 0) ? 1 : 0;
    }
    if (i < N_NODES) g_degi[i] = 0;
}

__device__ __forceinline__ void load_edge(const void* ei_raw, int e, int& s, int& d) {
    if (g_is64) {
        const long long* ei = (const long long*)ei_raw;
        s = (int)ei[e];
        d = (int)ei[NE + e];
    } else {
        const int* ei = (const int*)ei_raw;
        s = ei[e];
        d = ei[NE + e];
    }
}

// ---------------------------------------------------------------------------
// One GEMM tile, W already staged in w_sh. Per-warp C staging in csh
// (16 x 64 floats per warp), done in two 64-col halves.
// ---------------------------------------------------------------------------
__device__ __forceinline__ void gemm_tile_body(int tile, const float* __restrict__ X,
                                               const float* w_sh, float* csh) {
    int tid  = threadIdx.x;
    int warp = tid >> 5;
    int lane = tid & 31;

    int row0 = tile * 128 + warp * 16;
    if (row0 >= N_NODES) return;

    wmma::fragment<wmma::accumulator, 16, 16, 8, float> c[8];
#pragma unroll
    for (int n = 0; n < 8; n++) wmma::fill_fragment(c[n], 0.0f);

    const float* a_base = X + (size_t)row0 * D;
#pragma unroll 1
    for (int kc = 0; kc < 16; kc++) {
        wmma::fragment<wmma::matrix_a, 16, 16, 8, wmma::precision::tf32, wmma::row_major> a;
        wmma::load_matrix_sync(a, a_base + kc * 8, D);
#pragma unroll
        for (int t = 0; t < a.num_elements; t++) a.x[t] = wmma::__float_to_tf32(a.x[t]);
#pragma unroll
        for (int n = 0; n < 8; n++) {
            wmma::fragment<wmma::matrix_b, 16, 16, 8, wmma::precision::tf32, wmma::row_major> b;
            wmma::load_matrix_sync(b, w_sh + (kc * 8) * D + n * 16, D);
#pragma unroll
            for (int t = 0; t < b.num_elements; t++) b.x[t] = wmma::__float_to_tf32(b.x[t]);
            wmma::mma_sync(c[n], a, b, c[n]);
        }
    }

    float* cstg = csh + warp * 16 * 64;   // 16 rows x 64 cols
#pragma unroll
    for (int h = 0; h < 2; h++) {
#pragma unroll
        for (int n = 0; n < 4; n++)
            wmma::store_matrix_sync(cstg + n * 16, c[h * 4 + n], 64, wmma::mem_row_major);
        __syncwarp();
        // write 16 rows x 64 cols: lane covers 2 cols (one half2) per row
#pragma unroll
        for (int r = 0; r < 16; r++) {
            float2 v = ((const float2*)(cstg + r * 64))[lane];
            __half2 hp = __float22half2_rn(v);
            ((unsigned*)(g_Yh + (size_t)(row0 + r) * D + h * 64))[lane] = *(unsigned*)&hp;
        }
        __syncwarp();
    }
}

// ---------------------------------------------------------------------------
// fused_A: blocks [0,296) = persistent GEMM (tiles strided by 296, W staged
// once per block); blocks [296,...) = degree count.
// ---------------------------------------------------------------------------
__global__ void __launch_bounds__(256)
fused_A_kernel(const float* __restrict__ X, const float* __restrict__ W,
               const void* __restrict__ ei_raw) {
    extern __shared__ float sh[];
    if (blockIdx.x < GEMM_BLOCKS) {
        float* w_sh = sh;
        float* csh  = sh + SMEM_W_FLOATS;
        int tid = threadIdx.x;
        const float4* W4  = (const float4*)W;
        float4*       sh4 = (float4*)w_sh;
#pragma unroll
        for (int i = 0; i < 16; i++) sh4[tid + i * 256] = W4[tid + i * 256];
        __syncthreads();
#pragma unroll 1
        for (int tile = blockIdx.x; tile < GEMM_TILES; tile += GEMM_BLOCKS)
            gemm_tile_body(tile, X, w_sh, csh);
        return;
    }
    int cb   = blockIdx.x - GEMM_BLOCKS;
    int base = cb * 1024 + threadIdx.x;
#pragma unroll
    for (int j = 0; j < 4; j++) {
        int e = base + j * 256;
        if (e < NE) {
            int s, d;
            load_edge(ei_raw, e, s, d);
            atomicAdd(&g_degi[s], 1);
            atomicAdd(&g_degi[d], 1);
        }
    }
}

// ---------------------------------------------------------------------------
// Single-launch exclusive scan: degi -> rowstart (+cursor).
// 49 co-resident blocks; grid barrier via monotonic counter.
// ---------------------------------------------------------------------------
__global__ void __launch_bounds__(256)
scan_kernel() {
    int tid  = threadIdx.x;
    int b    = blockIdx.x;
    int lane = tid & 31;
    int warp = tid >> 5;
    int i0   = b * 2048 + tid * 8;

    int v[8];
    if (i0 < N_NODES) {   // N % 8 == 0
        int4 p0 = *(const int4*)(g_degi + i0);
        int4 p1 = *(const int4*)(g_degi + i0 + 4);
        v[0] = p0.x; v[1] = p0.y; v[2] = p0.z; v[3] = p0.w;
        v[4] = p1.x; v[5] = p1.y; v[6] = p1.z; v[7] = p1.w;
    } else {
#pragma unroll
        for (int k = 0; k < 8; k++) v[k] = 0;
    }

    int lp[8], s = 0;
#pragma unroll
    for (int k = 0; k < 8; k++) { lp[k] = s; s += v[k]; }

    int incl = s;
#pragma unroll
    for (int off = 1; off < 32; off <<= 1) {
        int t = __shfl_up_sync(0xffffffffu, incl, off);
        if (lane >= off) incl += t;
    }
    int wexcl = incl - s;

    __shared__ int wtot[8], wbase[8];
    if (lane == 31) wtot[warp] = incl;
    __syncthreads();
    if (tid == 0) {
        int acc = 0;
#pragma unroll
        for (int w = 0; w < 8; w++) { wbase[w] = acc; acc += wtot[w]; }
        g_bsum[b] = acc;
        __threadfence();
        unsigned my     = atomicAdd(&g_sync, 1u);
        unsigned target = (my / SCAN_BLOCKS + 1u) * SCAN_BLOCKS;
        while (atomicAdd(&g_sync, 0u) < target) __nanosleep(64);
    }
    __syncthreads();

    int part = 0;
    for (int j = lane; j < b; j += 32) part += __ldcg(&g_bsum[j]);
#pragma unroll
    for (int off = 16; off >= 1; off >>= 1)
        part += __shfl_xor_sync(0xffffffffu, part, off);
    int base = part;

    if (i0 < N_NODES) {
        int tb = base + wbase[warp] + wexcl;
        int4 r0, r1;
        r0.x = tb + lp[0]; r0.y = tb + lp[1]; r0.z = tb + lp[2]; r0.w = tb + lp[3];
        r1.x = tb + lp[4]; r1.y = tb + lp[5]; r1.z = tb + lp[6]; r1.w = tb + lp[7];
        *(int4*)(g_rowstart + i0)     = r0;
        *(int4*)(g_rowstart + i0 + 4) = r1;
        *(int4*)(g_cursor + i0)       = r0;
        *(int4*)(g_cursor + i0 + 4)   = r1;
    }
}

// ---------------------------------------------------------------------------
// fill: standalone, lean (no smem, low regs -> full occupancy).
// ---------------------------------------------------------------------------
__global__ void __launch_bounds__(256)
fill_kernel(const void* __restrict__ ei_raw) {
    int base = blockIdx.x * 1024 + threadIdx.x;
#pragma unroll
    for (int j = 0; j < 4; j++) {
        int e = base + j * 256;
        if (e < NE) {
            int s, d;
            load_edge(ei_raw, e, s, d);
            int p = atomicAdd(&g_cursor[s], 1);
            g_adj[p] = d;
            int q = atomicAdd(&g_cursor[d], 1);
            g_adj[q] = s;
        }
    }
}

// ---------------------------------------------------------------------------
// Gather (pure): out[i] = relu((Y[i] + sum_nbr Y[j]) / deg[i])
// ---------------------------------------------------------------------------
__device__ __forceinline__ void acc_half4(float4& acc, uint2 raw) {
    __half2 h01 = *(__half2*)&raw.x;
    __half2 h23 = *(__half2*)&raw.y;
    float2 f01 = __half22float2(h01);
    float2 f23 = __half22float2(h23);
    acc.x += f01.x; acc.y += f01.y; acc.z += f23.x; acc.w += f23.y;
}

__global__ void __launch_bounds__(256)
gather_kernel(float* __restrict__ out) {
    int w    = (blockIdx.x * blockDim.x + threadIdx.x) >> 5;
    int lane = threadIdx.x & 31;
    if (w >= N_NODES) return;

    int base = g_rowstart[w];
    int degn = g_degi[w];

    const uint2* Y2 = (const uint2*)g_Yh;
    float4 acc = make_float4(0.f, 0.f, 0.f, 0.f);
    acc_half4(acc, __ldg(Y2 + (size_t)w * 32 + lane));   // self term

    for (int t = 0; t < degn; t += 32) {
        int cnt   = min(32, degn - t);
        int myidx = (lane < cnt) ? g_adj[base + t + lane] : 0;
#pragma unroll 8
        for (int k = 0; k < cnt; k++) {
            int u = __shfl_sync(0xffffffffu, myidx, k);
            acc_half4(acc, __ldg(Y2 + (size_t)u * 32 + lane));
        }
    }

    float inv = 1.0f / (float)degn;
    float4 o;
    o.x = fmaxf(acc.x * inv, 0.0f);
    o.y = fmaxf(acc.y * inv, 0.0f);
    o.z = fmaxf(acc.z * inv, 0.0f);
    o.w = fmaxf(acc.w * inv, 0.0f);
    ((float4*)out)[(size_t)w * 32 + lane] = o;
}

// ---------------------------------------------------------------------------
extern "C" void kernel_launch(void* const* d_in, const int* in_sizes, int n_in,
                              void* d_out, int out_size) {
    const float* X   = (const float*)d_in[0];
    const float* W   = (const float*)d_in[1];
    const void*  EI  = d_in[2];
    float*       out = (float*)d_out;

    cudaFuncSetAttribute(fused_A_kernel,
                         cudaFuncAttributeMaxDynamicSharedMemorySize, SMEM_TOTAL_B);

    probe_zero_kernel<<<NB, 256>>>((const int*)EI);
    fused_A_kernel<<<GEMM_BLOCKS + EDGE_BLOCKS, 256, SMEM_TOTAL_B>>>(X, W, EI);
    scan_kernel<<<SCAN_BLOCKS, 256>>>();
    fill_kernel<<<EDGE_BLOCKS, 256>>>(EI);
    gather_kernel<<<(N_NODES * 32 + 255) / 256, 256>>>(out);
}

// round 12
// speedup vs baseline: 1.1034x; 1.1034x over previous
#include <cuda_runtime.h>
#include <cuda_fp16.h>
#include <mma.h>
#include <cstdint>

using namespace nvcuda;

#define N_NODES 100000
#define NE      1600000
#define D       128
#define NB      ((N_NODES + 255) / 256)

#define GEMM_TILES    782                 // 128 rows each
#define GEMM_BLOCKS   296                 // persistent: 2 per SM x 148
#define EDGE_BLOCKS8  782                 // 2048 edges per block (256 thr x 8)
#define SCAN_BLOCKS   49                  // 2048 nodes per block

// smem for GEMM: W (64 KB) + C staging (32 KB) = 96 KB
#define SMEM_W_FLOATS (D * D)
#define SMEM_C_FLOATS (8 * 16 * 64)
#define SMEM_GEMM     ((SMEM_W_FLOATS + SMEM_C_FLOATS) * (int)sizeof(float))

// Scratch (__device__ globals; no allocation)
__device__ __align__(16) __half g_Yh[(size_t)N_NODES * D];  // 25.6 MB
__device__ int g_degi[N_NODES];
__device__ int g_rowstart[N_NODES];
__device__ int g_cursor[N_NODES];
__device__ int g_adj[2 * NE];              // 12.8 MB
__device__ int g_bsum[SCAN_BLOCKS];
__device__ unsigned int g_sync;            // monotonic across calls; never reset
__device__ int g_is64;

// ---------------------------------------------------------------------------
// probe (thread 0) + zero degrees.
// ---------------------------------------------------------------------------
__global__ void probe_zero_kernel(const int* __restrict__ ei) {
    int i = blockIdx.x * blockDim.x + threadIdx.x;
    if (i == 0) {
        int acc = 0;
#pragma unroll
        for (int k = 1; k < 32; k += 2) acc |= ei[k];
        g_is64 = (acc == 0) ? 1 : 0;
    }
    if (i < N_NODES) g_degi[i] = 0;
}

__device__ __forceinline__ void load_edge(const void* ei_raw, bool is64,
                                          int e, int& s, int& d) {
    if (is64) {
        const long long* ei = (const long long*)ei_raw;
        s = (int)ei[e];
        d = (int)ei[NE + e];
    } else {
        const int* ei = (const int*)ei_raw;
        s = ei[e];
        d = ei[NE + e];
    }
}

// ---------------------------------------------------------------------------
// count: 8 edges/thread, loads batched up-front for MLP.
// ---------------------------------------------------------------------------
__global__ void __launch_bounds__(256)
count_kernel(const void* __restrict__ ei_raw) {
    bool is64 = (g_is64 != 0);
    int base  = blockIdx.x * 2048 + threadIdx.x;
    int s[8], d[8];
    bool ok[8];
#pragma unroll
    for (int j = 0; j < 8; j++) {
        int e = base + j * 256;
        ok[j] = (e < NE);
        if (ok[j]) load_edge(ei_raw, is64, e, s[j], d[j]);
    }
#pragma unroll
    for (int j = 0; j < 8; j++) {
        if (ok[j]) {
            atomicAdd(&g_degi[s[j]], 1);
            atomicAdd(&g_degi[d[j]], 1);
        }
    }
}

// ---------------------------------------------------------------------------
// Single-launch exclusive scan: degi -> rowstart (+cursor).
// 49 co-resident blocks; grid barrier via monotonic counter.
// ---------------------------------------------------------------------------
__global__ void __launch_bounds__(256)
scan_kernel() {
    int tid  = threadIdx.x;
    int b    = blockIdx.x;
    int lane = tid & 31;
    int warp = tid >> 5;
    int i0   = b * 2048 + tid * 8;

    int v[8];
    if (i0 < N_NODES) {   // N % 8 == 0
        int4 p0 = *(const int4*)(g_degi + i0);
        int4 p1 = *(const int4*)(g_degi + i0 + 4);
        v[0] = p0.x; v[1] = p0.y; v[2] = p0.z; v[3] = p0.w;
        v[4] = p1.x; v[5] = p1.y; v[6] = p1.z; v[7] = p1.w;
    } else {
#pragma unroll
        for (int k = 0; k < 8; k++) v[k] = 0;
    }

    int lp[8], s = 0;
#pragma unroll
    for (int k = 0; k < 8; k++) { lp[k] = s; s += v[k]; }

    int incl = s;
#pragma unroll
    for (int off = 1; off < 32; off <<= 1) {
        int t = __shfl_up_sync(0xffffffffu, incl, off);
        if (lane >= off) incl += t;
    }
    int wexcl = incl - s;

    __shared__ int wtot[8], wbase[8];
    if (lane == 31) wtot[warp] = incl;
    __syncthreads();
    if (tid == 0) {
        int acc = 0;
#pragma unroll
        for (int w = 0; w < 8; w++) { wbase[w] = acc; acc += wtot[w]; }
        g_bsum[b] = acc;
        __threadfence();
        unsigned my     = atomicAdd(&g_sync, 1u);
        unsigned target = (my / SCAN_BLOCKS + 1u) * SCAN_BLOCKS;
        while (atomicAdd(&g_sync, 0u) < target) __nanosleep(64);
    }
    __syncthreads();

    int part = 0;
    for (int j = lane; j < b; j += 32) part += __ldcg(&g_bsum[j]);
#pragma unroll
    for (int off = 16; off >= 1; off >>= 1)
        part += __shfl_xor_sync(0xffffffffu, part, off);
    int base = part;

    if (i0 < N_NODES) {
        int tb = base + wbase[warp] + wexcl;
        int4 r0, r1;
        r0.x = tb + lp[0]; r0.y = tb + lp[1]; r0.z = tb + lp[2]; r0.w = tb + lp[3];
        r1.x = tb + lp[4]; r1.y = tb + lp[5]; r1.z = tb + lp[6]; r1.w = tb + lp[7];
        *(int4*)(g_rowstart + i0)     = r0;
        *(int4*)(g_rowstart + i0 + 4) = r1;
        *(int4*)(g_cursor + i0)       = r0;
        *(int4*)(g_cursor + i0 + 4)   = r1;
    }
}

// ---------------------------------------------------------------------------
// fill: 8 edges/thread, loads batched up-front for MLP.
// ---------------------------------------------------------------------------
__global__ void __launch_bounds__(256)
fill_kernel(const void* __restrict__ ei_raw) {
    bool is64 = (g_is64 != 0);
    int base  = blockIdx.x * 2048 + threadIdx.x;
    int s[8], d[8];
    bool ok[8];
#pragma unroll
    for (int j = 0; j < 8; j++) {
        int e = base + j * 256;
        ok[j] = (e < NE);
        if (ok[j]) load_edge(ei_raw, is64, e, s[j], d[j]);
    }
#pragma unroll
    for (int j = 0; j < 8; j++) {
        if (ok[j]) {
            int p = atomicAdd(&g_cursor[s[j]], 1);
            g_adj[p] = d[j];
            int q = atomicAdd(&g_cursor[d[j]], 1);
            g_adj[q] = s[j];
        }
    }
}

// ---------------------------------------------------------------------------
// Persistent GEMM: Yh = half(X @ W), tf32 wmma, W staged once per block.
// ---------------------------------------------------------------------------
__device__ __forceinline__ void gemm_tile_body(int tile, const float* __restrict__ X,
                                               const float* w_sh, float* csh) {
    int tid  = threadIdx.x;
    int warp = tid >> 5;
    int lane = tid & 31;

    int row0 = tile * 128 + warp * 16;
    if (row0 >= N_NODES) return;

    wmma::fragment<wmma::accumulator, 16, 16, 8, float> c[8];
#pragma unroll
    for (int n = 0; n < 8; n++) wmma::fill_fragment(c[n], 0.0f);

    const float* a_base = X + (size_t)row0 * D;
#pragma unroll 1
    for (int kc = 0; kc < 16; kc++) {
        wmma::fragment<wmma::matrix_a, 16, 16, 8, wmma::precision::tf32, wmma::row_major> a;
        wmma::load_matrix_sync(a, a_base + kc * 8, D);
#pragma unroll
        for (int t = 0; t < a.num_elements; t++) a.x[t] = wmma::__float_to_tf32(a.x[t]);
#pragma unroll
        for (int n = 0; n < 8; n++) {
            wmma::fragment<wmma::matrix_b, 16, 16, 8, wmma::precision::tf32, wmma::row_major> b;
            wmma::load_matrix_sync(b, w_sh + (kc * 8) * D + n * 16, D);
#pragma unroll
            for (int t = 0; t < b.num_elements; t++) b.x[t] = wmma::__float_to_tf32(b.x[t]);
            wmma::mma_sync(c[n], a, b, c[n]);
        }
    }

    float* cstg = csh + warp * 16 * 64;
#pragma unroll
    for (int h = 0; h < 2; h++) {
#pragma unroll
        for (int n = 0; n < 4; n++)
            wmma::store_matrix_sync(cstg + n * 16, c[h * 4 + n], 64, wmma::mem_row_major);
        __syncwarp();
#pragma unroll
        for (int r = 0; r < 16; r++) {
            float2 v = ((const float2*)(cstg + r * 64))[lane];
            __half2 hp = __float22half2_rn(v);
            ((unsigned*)(g_Yh + (size_t)(row0 + r) * D + h * 64))[lane] = *(unsigned*)&hp;
        }
        __syncwarp();
    }
}

__global__ void __launch_bounds__(256)
gemm_kernel(const float* __restrict__ X, const float* __restrict__ W) {
    extern __shared__ float sh[];
    float* w_sh = sh;
    float* csh  = sh + SMEM_W_FLOATS;
    int tid = threadIdx.x;
    const float4* W4  = (const float4*)W;
    float4*       sh4 = (float4*)w_sh;
#pragma unroll
    for (int i = 0; i < 16; i++) sh4[tid + i * 256] = W4[tid + i * 256];
    __syncthreads();
#pragma unroll 1
    for (int tile = blockIdx.x; tile < GEMM_TILES; tile += GEMM_BLOCKS)
        gemm_tile_body(tile, X, w_sh, csh);
}

// ---------------------------------------------------------------------------
// Gather (pure): out[i] = relu((Y[i] + sum_nbr Y[j]) / deg[i])
// ---------------------------------------------------------------------------
__device__ __forceinline__ void acc_half4(float4& acc, uint2 raw) {
    __half2 h01 = *(__half2*)&raw.x;
    __half2 h23 = *(__half2*)&raw.y;
    float2 f01 = __half22float2(h01);
    float2 f23 = __half22float2(h23);
    acc.x += f01.x; acc.y += f01.y; acc.z += f23.x; acc.w += f23.y;
}

__global__ void __launch_bounds__(256)
gather_kernel(float* __restrict__ out) {
    int w    = (blockIdx.x * blockDim.x + threadIdx.x) >> 5;
    int lane = threadIdx.x & 31;
    if (w >= N_NODES) return;

    int base = g_rowstart[w];
    int degn = g_degi[w];

    const uint2* Y2 = (const uint2*)g_Yh;
    float4 acc = make_float4(0.f, 0.f, 0.f, 0.f);
    acc_half4(acc, __ldg(Y2 + (size_t)w * 32 + lane));   // self term

    for (int t = 0; t < degn; t += 32) {
        int cnt   = min(32, degn - t);
        int myidx = (lane < cnt) ? g_adj[base + t + lane] : 0;
#pragma unroll 8
        for (int k = 0; k < cnt; k++) {
            int u = __shfl_sync(0xffffffffu, myidx, k);
            acc_half4(acc, __ldg(Y2 + (size_t)u * 32 + lane));
        }
    }

    float inv = 1.0f / (float)degn;
    float4 o;
    o.x = fmaxf(acc.x * inv, 0.0f);
    o.y = fmaxf(acc.y * inv, 0.0f);
    o.z = fmaxf(acc.z * inv, 0.0f);
    o.w = fmaxf(acc.w * inv, 0.0f);
    ((float4*)out)[(size_t)w * 32 + lane] = o;
}

// ---------------------------------------------------------------------------
// Launch: fork the CSR chain onto a side stream so it runs concurrently with
// the persistent GEMM (event-linked; graph capture turns these into parallel
// graph branches). Streams/events are created per call and not destroyed
// (host handles only, no device memory).
// ---------------------------------------------------------------------------
extern "C" void kernel_launch(void* const* d_in, const int* in_sizes, int n_in,
                              void* d_out, int out_size) {
    const float* X   = (const float*)d_in[0];
    const float* W   = (const float*)d_in[1];
    const void*  EI  = d_in[2];
    float*       out = (float*)d_out;

    cudaFuncSetAttribute(gemm_kernel,
                         cudaFuncAttributeMaxDynamicSharedMemorySize, SMEM_GEMM);

    cudaStream_t s2;
    cudaStreamCreateWithFlags(&s2, cudaStreamNonBlocking);
    cudaEvent_t evFork, evCsr;
    cudaEventCreateWithFlags(&evFork, cudaEventDisableTiming);
    cudaEventCreateWithFlags(&evCsr, cudaEventDisableTiming);

    // fork
    cudaEventRecord(evFork, 0);
    cudaStreamWaitEvent(s2, evFork, 0);

    // s2: CSR chain (latency/atomic-bound)
    probe_zero_kernel<<<NB, 256, 0, s2>>>((const int*)EI);
    count_kernel<<<EDGE_BLOCKS8, 256, 0, s2>>>(EI);
    scan_kernel<<<SCAN_BLOCKS, 256, 0, s2>>>();
    fill_kernel<<<EDGE_BLOCKS8, 256, 0, s2>>>(EI);
    cudaEventRecord(evCsr, s2);

    // s0: persistent GEMM (tensor-bound), concurrent with CSR chain
    gemm_kernel<<<GEMM_BLOCKS, 256, SMEM_GEMM>>>(X, W);

    // join, then gather
    cudaStreamWaitEvent(0, evCsr, 0);
    gather_kernel<<<(N_NODES * 32 + 255) / 256, 256>>>(out);
}